// round 11
// baseline (speedup 1.0000x reference)
#include <cuda_runtime.h>
#include <cstdint>

// AttentionLayer: B=2048, N=64, D=256, H=16
//   m_i[h]  = sum_d members[b,i,d]*item[b,d]*W1[d,h]
//   s[h]    = sum_i m_i[h] ; pre = 64*m_i - s + b1 ; relu ; logit = relu@W2 + b2
//   out[b,i] = softmax_i(logit)
//
// R11 (= R10 resubmitted unchanged; previous round was an infra failure):
// zero-duplication LDS mapping. Block = 64 thr = 2 warps = 1 batch. Warp p
// owns heads 8p..8p+7; lane owns d in [8*lane, 8*lane+8) x all 8 heads
// (wreg = 32 ull). Rows stored in smem with even/odd 16B-chunk permutation so
// a full 1KB row is read with TWO contiguous conflict-free LDS.128 per warp
// (8 wavefronts/row vs 32 in R8). Per-row head sums via 5-level reduce-scatter
// butterfly; lane ends holding m[(row=bit4, head=(lane>>1)&7)]. Private
// per-warp cp.async ring (4 slots x 2 rows), no block barriers in main loop.

constexpr int Bb = 2048;
constexpr int Nn = 64;
constexpr int Dd = 256;
constexpr int Hh = 16;
constexpr int THREADS = 64;
constexpr int RING = 4;                // slots of 2 rows (2 KB) per warp
constexpr int MSTR = 25;               // mS row stride (odd -> conflict-free epilogue)

typedef unsigned long long ull;

#define FMA2(acc, a, w)  asm("fma.rn.f32x2 %0, %1, %2, %0;" : "+l"(acc) : "l"(a), "l"(w))
#define ADD2(d, a, b_)   asm("add.rn.f32x2 %0, %1, %2;" : "=l"(d) : "l"(a), "l"(b_))
#define PACK2(d, lo, hi) asm("mov.b64 %0, {%1, %2};" : "=l"(d) : "f"(lo), "f"(hi))
#define UNPACK2(lo, hi, v) asm("mov.b64 {%0, %1}, %2;" : "=f"(lo), "=f"(hi) : "l"(v))

__device__ __forceinline__ uint32_t smem_u32(const void* p) {
    uint32_t a;
    asm("{ .reg .u64 t; cvta.to.shared.u64 t, %1; cvt.u32.u64 %0, t; }"
        : "=r"(a) : "l"(p));
    return a;
}
__device__ __forceinline__ void cp_async16(uint32_t dst, const void* src) {
    asm volatile("cp.async.cg.shared.global [%0], [%1], 16;" :: "r"(dst), "l"(src));
}
__device__ __forceinline__ void cp_commit() {
    asm volatile("cp.async.commit_group;" ::: "memory");
}
__device__ __forceinline__ void cp_wait2() {
    asm volatile("cp.async.wait_group %0;" :: "n"(RING - 2) : "memory");
}

__global__ __launch_bounds__(THREADS, 8)
void attn_kernel(const float* __restrict__ members,
                 const float* __restrict__ item,
                 const float* __restrict__ W1,
                 const float* __restrict__ b1,
                 const float* __restrict__ W2,
                 const float* __restrict__ b2,
                 float* __restrict__ out)
{
    __shared__ float4 ring[2][RING][2][64];    // [warp][slot][row][16B chunk] = 16 KB
    __shared__ float  mS[Nn * MSTR];           // 6.4 KB (warps write disjoint heads)
    __shared__ float  sS[Hh];
    __shared__ float  red[2][2];               // [max|sum][warp]

    const int tid  = threadIdx.x;
    const int p    = tid >> 5;                 // warp: heads 8p..8p+7
    const int lane = tid & 31;
    const int b    = blockIdx.x;

    const int rKeep = (lane >> 4) & 1;         // final row-ownership bit
    const int lb3 = (lane >> 3) & 1;
    const int lb2 = (lane >> 2) & 1;
    const int lb1 = (lane >> 1) & 1;
    const int hOwn = (lane >> 1) & 7;          // final head owned (within warp)

    const float4* grow = (const float4*)(members + (size_t)b * Nn * Dd);
    const uint32_t ringBase = smem_u32(&ring[p][0][0][0]);
    // fill permutation: gmem chunk c -> smem slot (c&1)*32 + (c>>1)
    const uint32_t fillOff = (((lane & 1) << 5) + (lane >> 1)) * 16;

    // ---- prologue: slots 0..2 (rows 0..5) in flight ----
    #pragma unroll
    for (int it = 0; it < RING - 1; it++) {
        #pragma unroll
        for (int rr = 0; rr < 2; rr++) {
            const uint32_t d0 = ringBase + it * 2048 + rr * 1024 + fillOff;
            const float4* g = grow + (2 * it + rr) * 64;
            cp_async16(d0,       g + lane);        // chunk lane    -> permuted slot
            cp_async16(d0 + 256, g + lane + 32);   // chunk lane+32 -> permuted slot
        }
        cp_commit();
    }

    // ---- register weights: lane's 8 d x 8 heads, d-pair packed ----
    // wreg[k*8+c] = (W1[d0][8p+c]*it[d0], W1[d0+1][8p+c]*it[d0+1]), d0 = 8*lane+2k
    const float* itG = item + (size_t)b * Dd;
    const int dbase = 8 * lane;
    ull wreg[32];
    #pragma unroll
    for (int k = 0; k < 4; k++) {
        const int d0 = dbase + 2 * k;
        const float i0 = __ldg(&itG[d0]);
        const float i1 = __ldg(&itG[d0 + 1]);
        const float4 a0 = __ldg((const float4*)&W1[d0 * Hh + 8 * p]);
        const float4 a1 = __ldg((const float4*)&W1[d0 * Hh + 8 * p + 4]);
        const float4 c0 = __ldg((const float4*)&W1[(d0 + 1) * Hh + 8 * p]);
        const float4 c1 = __ldg((const float4*)&W1[(d0 + 1) * Hh + 8 * p + 4]);
        PACK2(wreg[k * 8 + 0], a0.x * i0, c0.x * i1);
        PACK2(wreg[k * 8 + 1], a0.y * i0, c0.y * i1);
        PACK2(wreg[k * 8 + 2], a0.z * i0, c0.z * i1);
        PACK2(wreg[k * 8 + 3], a0.w * i0, c0.w * i1);
        PACK2(wreg[k * 8 + 4], a1.x * i0, c1.x * i1);
        PACK2(wreg[k * 8 + 5], a1.y * i0, c1.y * i1);
        PACK2(wreg[k * 8 + 6], a1.z * i0, c1.z * i1);
        PACK2(wreg[k * 8 + 7], a1.w * i0, c1.w * i1);
    }

    // ---- main loop: 32 iterations x 2 rows, no block barriers ----
    float sAcc = 0.f;
    for (int i = 0; i < Nn / 2; i++) {
        cp_wait2();                 // slot i&3 landed (<=2 newer groups pending)
        __syncwarp();               // all lanes' fills visible; prior reads done

        if (i + RING - 1 < Nn / 2) {   // refill slot (i-1)&3 with iter i+3
            const int it = i + RING - 1;
            #pragma unroll
            for (int rr = 0; rr < 2; rr++) {
                const uint32_t d0 = ringBase + (it & 3) * 2048 + rr * 1024 + fillOff;
                const float4* g = grow + (2 * it + rr) * 64;
                cp_async16(d0,       g + lane);
                cp_async16(d0 + 256, g + lane + 32);
            }
        }
        cp_commit();                // unconditional: wait arithmetic stays exact

        ull P[2][4];
        #pragma unroll
        for (int rr = 0; rr < 2; rr++) {
            const ulonglong2* sp = (const ulonglong2*)&ring[p][i & 3][rr][0];
            const ulonglong2 u0 = sp[lane];        // even chunks: d[8l..8l+4)
            const ulonglong2 u1 = sp[32 + lane];   // odd chunks:  d[8l+4..8l+8)
            const ull dp[4] = {u0.x, u0.y, u1.x, u1.y};

            ull acc[8] = {0,0,0,0,0,0,0,0};
            #pragma unroll
            for (int k = 0; k < 4; k++) {
                #pragma unroll
                for (int c = 0; c < 8; c++)
                    FMA2(acc[c], dp[k], wreg[k * 8 + c]);
            }
            float mh[8];
            #pragma unroll
            for (int c = 0; c < 8; c++) {
                float x, y;
                UNPACK2(x, y, acc[c]);
                mh[c] = x + y;
            }
            PACK2(P[rr][0], mh[0], mh[1]);
            PACK2(P[rr][1], mh[2], mh[3]);
            PACK2(P[rr][2], mh[4], mh[5]);
            PACK2(P[rr][3], mh[6], mh[7]);
        }

        // ---- reduce-scatter butterfly: 32 lanes -> 16 outputs (2 rows x 8 heads)
        ull Q[4], R[2], S;
        #pragma unroll
        for (int cc = 0; cc < 4; cc++) {           // level xor16: keep row rKeep
            const ull snd  = rKeep ? P[0][cc] : P[1][cc];
            const ull kept = rKeep ? P[1][cc] : P[0][cc];
            const ull rcv = __shfl_xor_sync(0xffffffffu, snd, 16);
            ADD2(Q[cc], kept, rcv);
        }
        #pragma unroll
        for (int j = 0; j < 2; j++) {              // level xor8: keep pair-group lb3
            const ull snd  = lb3 ? Q[j] : Q[2 + j];
            const ull kept = lb3 ? Q[2 + j] : Q[j];
            const ull rcv = __shfl_xor_sync(0xffffffffu, snd, 8);
            ADD2(R[j], kept, rcv);
        }
        {                                          // level xor4: keep pair lb2
            const ull snd  = lb2 ? R[0] : R[1];
            const ull kept = lb2 ? R[1] : R[0];
            const ull rcv = __shfl_xor_sync(0xffffffffu, snd, 4);
            ADD2(S, kept, rcv);
        }
        float x, y;                                // level xor2: split the pair
        UNPACK2(x, y, S);
        const float fsnd  = lb1 ? x : y;
        const float fkeep = lb1 ? y : x;
        float m2 = fkeep + __shfl_xor_sync(0xffffffffu, fsnd, 2);
        const float m = m2 + __shfl_xor_sync(0xffffffffu, m2, 1);  // xor1: final

        sAcc += m;                  // lane's head hOwn, rows == rKeep (mod 2)
        if (!(lane & 1))
            mS[(2 * i + rKeep) * MSTR + 8 * p + hOwn] = m;
    }

    // s reduce: combine the two row-parity groups (bit4)
    const float sFull = sAcc + __shfl_xor_sync(0xffffffffu, sAcc, 16);
    if (!(lane & 1) && lane < 16) sS[8 * p + (lane >> 1)] = sFull;
    __syncthreads();                // barrier #1: mS + sS complete

    // ---- epilogue: row = tid ----
    const int row = tid;
    float logit = __ldg(b2);
    #pragma unroll
    for (int hh = 0; hh < 16; hh++) {
        const float pre = 64.f * mS[row * MSTR + hh] + __ldg(&b1[hh]) - sS[hh];
        logit += fmaxf(pre, 0.f) * __ldg(&W2[hh]);
    }

    float mx = logit;
    #pragma unroll
    for (int o = 16; o >= 1; o >>= 1)
        mx = fmaxf(mx, __shfl_xor_sync(0xffffffffu, mx, o));
    if (lane == 0) red[0][p] = mx;
    __syncthreads();                // barrier #2
    const float mxAll = fmaxf(red[0][0], red[0][1]);

    const float e = __expf(logit - mxAll);
    float sm = e;
    #pragma unroll
    for (int o = 16; o >= 1; o >>= 1)
        sm += __shfl_xor_sync(0xffffffffu, sm, o);
    if (lane == 0) red[1][p] = sm;
    __syncthreads();                // barrier #3
    const float inv = 1.0f / (red[1][0] + red[1][1]);

    out[(size_t)b * Nn + row] = e * inv;
}

extern "C" void kernel_launch(void* const* d_in, const int* in_sizes, int n_in,
                              void* d_out, int out_size)
{
    attn_kernel<<<Bb, THREADS>>>(
        (const float*)d_in[0],   // members_embeds [2048,64,256]
        (const float*)d_in[1],   // item_embeds    [2048,256]
        (const float*)d_in[2],   // W1 [256,16]
        (const float*)d_in[3],   // b1 [16]
        (const float*)d_in[4],   // W2 [16,1]
        (const float*)d_in[5],   // b2 [1]
        (float*)d_out);          // out [2048,64]
}

// round 12
// speedup vs baseline: 1.5205x; 1.5205x over previous
#include <cuda_runtime.h>
#include <cstdint>

// AttentionLayer: B=2048, N=64, D=256, H=16
//   m_i[h]  = sum_d members[b,i,d]*item[b,d]*W1[d,h]
//   s[h]    = sum_i m_i[h] ; pre = 64*m_i - s + b1 ; relu ; logit = relu@W2 + b2
//   out[b,i] = softmax_i(logit)
//
// R12: R8 compute body (best: 45.2us) with the cp.async fills replaced by
// TMA bulk copies. One cp.async.bulk (4KB = 4 rows) per ring slot, issued by
// tid 0; full/empty mbarrier pairs; ring SHARED by both warps (single copy,
// no duplicate fills). Removes all LDGSTS wavefront+issue cost from the LSU.

constexpr int Bb = 2048;
constexpr int Nn = 64;
constexpr int Dd = 256;
constexpr int Hh = 16;
constexpr int THREADS = 64;
constexpr int NSLOT = 4;               // ring slots
constexpr int SROWS = 4;               // rows per slot (4 KB)
constexpr int ITERS = Nn / SROWS;      // 16
constexpr int MSTR = 18;               // mS row stride (72 B, 8B-aligned)

typedef unsigned long long ull;

#define FMA2(acc, a, w)  asm("fma.rn.f32x2 %0, %1, %2, %0;" : "+l"(acc) : "l"(a), "l"(w))
#define ADD2(d, a, b_)   asm("add.rn.f32x2 %0, %1, %2;" : "=l"(d) : "l"(a), "l"(b_))
#define PACK2(d, lo, hi) asm("mov.b64 %0, {%1, %2};" : "=l"(d) : "f"(lo), "f"(hi))
#define UNPACK2(lo, hi, v) asm("mov.b64 {%0, %1}, %2;" : "=f"(lo), "=f"(hi) : "l"(v))

__device__ __forceinline__ uint32_t smem_u32(const void* p) {
    uint32_t a;
    asm("{ .reg .u64 t; cvta.to.shared.u64 t, %1; cvt.u32.u64 %0, t; }"
        : "=r"(a) : "l"(p));
    return a;
}
__device__ __forceinline__ void mbar_init(uint32_t addr, uint32_t count) {
    asm volatile("mbarrier.init.shared.b64 [%0], %1;" :: "r"(addr), "r"(count) : "memory");
}
__device__ __forceinline__ void mbar_arrive(uint32_t addr) {
    asm volatile("mbarrier.arrive.shared.b64 _, [%0];" :: "r"(addr) : "memory");
}
__device__ __forceinline__ void mbar_expect_tx(uint32_t addr, uint32_t bytes) {
    asm volatile("mbarrier.arrive.expect_tx.shared.b64 _, [%0], %1;"
                 :: "r"(addr), "r"(bytes) : "memory");
}
__device__ __forceinline__ void mbar_wait(uint32_t addr, uint32_t phase) {
    asm volatile(
        "{\n\t.reg .pred P;\n\t"
        "W%=:\n\t"
        "mbarrier.try_wait.parity.acquire.cta.shared::cta.b64 P, [%0], %1, 0x989680;\n\t"
        "@P bra D%=;\n\t"
        "bra W%=;\n\t"
        "D%=:\n\t}"
        :: "r"(addr), "r"(phase) : "memory");
}
__device__ __forceinline__ void tma_bulk_1d(uint32_t dst, const void* src,
                                            uint32_t bytes, uint32_t mbar) {
    asm volatile(
        "cp.async.bulk.shared::cta.global.mbarrier::complete_tx::bytes [%0], [%1], %2, [%3];"
        :: "r"(dst), "l"(src), "r"(bytes), "r"(mbar) : "memory");
}

__global__ __launch_bounds__(THREADS, 8)
void attn_kernel(const float* __restrict__ members,
                 const float* __restrict__ item,
                 const float* __restrict__ W1,
                 const float* __restrict__ b1,
                 const float* __restrict__ W2,
                 const float* __restrict__ b2,
                 float* __restrict__ out)
{
    __shared__ __align__(16) float4 ringS[NSLOT][SROWS][Dd / 4];  // 16 KB shared ring
    __shared__ float  mS[Nn * MSTR];       // 4.6 KB (warps write disjoint heads)
    __shared__ float  sS[Hh];
    __shared__ float  red[2][2];           // [max|sum][warp]
    __shared__ __align__(8) ull mbar[2 * NSLOT];   // full[0..3], empty[4..7]

    const int tid  = threadIdx.x;
    const int p    = tid >> 5;             // warp: heads 8p..8p+7
    const int lane = tid & 31;
    const int hgrp = lane & 3;             // head pair within warp
    const int ds   = lane >> 2;            // d-eighth (quads 8t + ds)
    const int h0   = 8 * p + 2 * hgrp;     // lane's first head
    const int b    = blockIdx.x;

    const float* growF = members + (size_t)b * Nn * Dd;
    const uint32_t ringBase = smem_u32(&ringS[0][0][0]);
    const uint32_t mbarBase = smem_u32(&mbar[0]);
    #define FULL(s)  (mbarBase + (s) * 8)
    #define EMPTY(s) (mbarBase + (NSLOT + (s)) * 8)

    // ---- mbarrier init + prologue fills ----
    if (tid == 0) {
        #pragma unroll
        for (int s = 0; s < NSLOT; s++) {
            mbar_init(FULL(s), 1);         // 1 arrival: the expect_tx
            mbar_init(EMPTY(s), 2);        // 1 arrival per warp
        }
    }
    asm volatile("fence.proxy.async.shared::cta;" ::: "memory");
    __syncthreads();
    if (tid == 0) {
        #pragma unroll
        for (int s = 0; s < NSLOT; s++) {
            mbar_expect_tx(FULL(s), SROWS * Dd * 4);
            tma_bulk_1d(ringBase + s * 4096, growF + s * SROWS * Dd,
                        SROWS * Dd * 4, FULL(s));
        }
    }

    // ---- register weights: lane's 2 heads x 32 d (R8 layout) ----
    const float* itG = item + (size_t)b * Dd;
    ull wreg[32];
    #pragma unroll
    for (int t = 0; t < 8; t++) {
        const int d0 = (8 * t + ds) * 4;
        const float4 it4 = __ldg((const float4*)&itG[d0]);
        #pragma unroll
        for (int j = 0; j < 2; j++) {
            const int h = h0 + j;
            float w0 = __ldg(&W1[(d0 + 0) * Hh + h]) * it4.x;
            float w1 = __ldg(&W1[(d0 + 1) * Hh + h]) * it4.y;
            float w2 = __ldg(&W1[(d0 + 2) * Hh + h]) * it4.z;
            float w3 = __ldg(&W1[(d0 + 3) * Hh + h]) * it4.w;
            PACK2(wreg[4 * t + 2 * j],     w0, w1);
            PACK2(wreg[4 * t + 2 * j + 1], w2, w3);
        }
    }

    // ---- main loop: 16 iterations x 4 rows ----
    ull sAcc = 0ull;                       // packed (s_h0, s_h1), post-reduce
    for (int i = 0; i < ITERS; i++) {
        const int s  = i & (NSLOT - 1);
        const uint32_t ph = (i >> 2) & 1;  // slot reuse parity
        mbar_wait(FULL(s), ph);            // TMA delivered slot s (acquire)

        ull mm[4];
        #pragma unroll
        for (int rr = 0; rr < SROWS; rr++) {
            const ulonglong2* rp = (const ulonglong2*)&ringS[s][rr][0];
            ull a0 = 0ull, a1 = 0ull, a2 = 0ull, a3 = 0ull;
            #pragma unroll
            for (int t = 0; t < 8; t++) {
                const ulonglong2 u = rp[8 * t + ds];   // 128B contig, 4-way bcast
                FMA2(a0, u.x, wreg[4 * t + 0]);
                FMA2(a1, u.y, wreg[4 * t + 1]);
                FMA2(a2, u.x, wreg[4 * t + 2]);
                FMA2(a3, u.y, wreg[4 * t + 3]);
            }
            ADD2(a0, a0, a1);       // head0
            ADD2(a2, a2, a3);       // head1
            float x, y, m0, m1;
            UNPACK2(x, y, a0); m0 = x + y;
            UNPACK2(x, y, a2); m1 = x + y;
            PACK2(mm[rr], m0, m1);  // (m_h0, m_h1) for row 4i+rr
        }

        // 4 independent 3-level butterflies over the 8 ds lanes (xor 4,8,16)
        ull tmp;
        #pragma unroll
        for (int o = 4; o <= 16; o <<= 1) {
            tmp = __shfl_xor_sync(0xffffffffu, mm[0], o); ADD2(mm[0], mm[0], tmp);
            tmp = __shfl_xor_sync(0xffffffffu, mm[1], o); ADD2(mm[1], mm[1], tmp);
            tmp = __shfl_xor_sync(0xffffffffu, mm[2], o); ADD2(mm[2], mm[2], tmp);
            tmp = __shfl_xor_sync(0xffffffffu, mm[3], o); ADD2(mm[3], mm[3], tmp);
        }
        ADD2(sAcc, sAcc, mm[0]);
        ADD2(sAcc, sAcc, mm[1]);
        ADD2(sAcc, sAcc, mm[2]);
        ADD2(sAcc, sAcc, mm[3]);

        if (lane < 4) {             // ds==0 lanes publish their 2 heads x 4 rows
            #pragma unroll
            for (int rr = 0; rr < SROWS; rr++)
                *(ull*)&mS[(SROWS * i + rr) * MSTR + h0] = mm[rr];
        }

        __syncwarp();               // whole warp done reading slot s
        if (lane == 0) mbar_arrive(EMPTY(s));
        if (tid == 0 && i + NSLOT < ITERS) {
            mbar_wait(EMPTY(s), ph);               // both warps released slot s
            mbar_expect_tx(FULL(s), SROWS * Dd * 4);
            tma_bulk_1d(ringBase + s * 4096, growF + (i + NSLOT) * SROWS * Dd,
                        SROWS * Dd * 4, FULL(s));
        }
    }

    // sAcc fully reduced across lanes; lanes 0-3 publish 2 heads each
    if (lane < 4) *(ull*)&sS[h0] = sAcc;
    __syncthreads();                // barrier #1: mS + sS complete

    // ---- epilogue: row = tid ----
    const int row = tid;
    float logit = __ldg(b2);
    #pragma unroll
    for (int hh = 0; hh < 16; hh++) {
        const float pre = 64.f * mS[row * MSTR + hh] + __ldg(&b1[hh]) - sS[hh];
        logit += fmaxf(pre, 0.f) * __ldg(&W2[hh]);
    }

    float mx = logit;
    #pragma unroll
    for (int o = 16; o >= 1; o >>= 1)
        mx = fmaxf(mx, __shfl_xor_sync(0xffffffffu, mx, o));
    if (lane == 0) red[0][p] = mx;
    __syncthreads();                // barrier #2
    const float mxAll = fmaxf(red[0][0], red[0][1]);

    const float e = __expf(logit - mxAll);
    float sm = e;
    #pragma unroll
    for (int o = 16; o >= 1; o >>= 1)
        sm += __shfl_xor_sync(0xffffffffu, sm, o);
    if (lane == 0) red[1][p] = sm;
    __syncthreads();                // barrier #3
    const float inv = 1.0f / (red[1][0] + red[1][1]);

    out[(size_t)b * Nn + row] = e * inv;
}

extern "C" void kernel_launch(void* const* d_in, const int* in_sizes, int n_in,
                              void* d_out, int out_size)
{
    attn_kernel<<<Bb, THREADS>>>(
        (const float*)d_in[0],   // members_embeds [2048,64,256]
        (const float*)d_in[1],   // item_embeds    [2048,256]
        (const float*)d_in[2],   // W1 [256,16]
        (const float*)d_in[3],   // b1 [16]
        (const float*)d_in[4],   // W2 [16,1]
        (const float*)d_in[5],   // b2 [1]
        (float*)d_out);          // out [2048,64]
}